// round 14
// baseline (speedup 1.0000x reference)
#include <cuda_runtime.h>
#include <cuda_bf16.h>
#include <cuda_fp16.h>
#include <cstdint>

#define NMAX 100000
#define EMAX 1700000
#define F 128

// ------------------------- device-global scratch ---------------------------
__device__ __half g_s1h[(size_t)NMAX * F];   // fp16 gathered s1
__device__ __half g_s2h[(size_t)NMAX * F];   // fp16 gathered s2
__device__ float  g_x1[(size_t)NMAX * F];
__device__ float  g_x2[(size_t)NMAX * F];
__device__ __half g_xh[(size_t)NMAX * F];    // fp16 mirror of current layer input
__device__ int    g_off1[NMAX], g_cur1[NMAX];
__device__ int    g_off2[NMAX], g_cur2[NMAX];
__device__ int2   g_e1[EMAX], g_e2[EMAX];    // interleaved {src, w-bits}
__device__ int    g_part1[512], g_part2[512];

// ------------------------------- CSR build ---------------------------------
__global__ void hist_dual(const int* __restrict__ d1, int E1, int* __restrict__ c1,
                          const int* __restrict__ d2, int E2, int* __restrict__ c2)
{
    int i = blockIdx.x * blockDim.x + threadIdx.x;
    int stride = gridDim.x * blockDim.x;
    const int q1 = E1 >> 2, q2 = E2 >> 2;
    const int total = q1 + q2;
    for (int j = i; j < total; j += stride) {
        if (j < q1) {
            int4 v = __ldg((const int4*)d1 + j);
            atomicAdd(&c1[v.x], 1); atomicAdd(&c1[v.y], 1);
            atomicAdd(&c1[v.z], 1); atomicAdd(&c1[v.w], 1);
        } else {
            int4 v = __ldg((const int4*)d2 + (j - q1));
            atomicAdd(&c2[v.x], 1); atomicAdd(&c2[v.y], 1);
            atomicAdd(&c2[v.z], 1); atomicAdd(&c2[v.w], 1);
        }
    }
    if (i < (E1 & 3)) atomicAdd(&c1[d1[(q1 << 2) + i]], 1);
    else if (i >= 4 && i - 4 < (E2 & 3)) atomicAdd(&c2[d2[(q2 << 2) + i - 4]], 1);
}

__global__ void __launch_bounds__(512) scanA_kernel(
    const int* __restrict__ cnt1, int* __restrict__ off1, int* __restrict__ p1,
    const int* __restrict__ cnt2, int* __restrict__ off2, int* __restrict__ p2,
    int N)
{
    const int* cnt = blockIdx.y ? cnt2 : cnt1;
    int* off       = blockIdx.y ? off2 : off1;
    int* partial   = blockIdx.y ? p2   : p1;
    __shared__ int sh[512];
    int t = threadIdx.x;
    int i = blockIdx.x * 512 + t;
    int v = (i < N) ? cnt[i] : 0;
    sh[t] = v;
    __syncthreads();
#pragma unroll
    for (int d = 1; d < 512; d <<= 1) {
        int u = (t >= d) ? sh[t - d] : 0;
        __syncthreads();
        sh[t] += u;
        __syncthreads();
    }
    if (i < N) off[i] = sh[t] - v;
    if (t == 511) partial[blockIdx.x] = sh[511];
}

__global__ void __launch_bounds__(512) scanB_kernel(
    int* __restrict__ p1, int* __restrict__ p2, int NB)
{
    int* partial = blockIdx.x ? p2 : p1;
    __shared__ int sh[512];
    int t = threadIdx.x;
    int v = (t < NB) ? partial[t] : 0;
    sh[t] = v;
    __syncthreads();
#pragma unroll
    for (int d = 1; d < 512; d <<= 1) {
        int u = (t >= d) ? sh[t - d] : 0;
        __syncthreads();
        sh[t] += u;
        __syncthreads();
    }
    if (t < NB) partial[t] = sh[t] - v;
}

__global__ void scanC_kernel(int* __restrict__ off1, const int* __restrict__ p1,
                             int* __restrict__ cur1,
                             int* __restrict__ off2, const int* __restrict__ p2,
                             int* __restrict__ cur2, int N)
{
    int* off        = blockIdx.y ? off2 : off1;
    const int* pb   = blockIdx.y ? p2   : p1;
    int* cur        = blockIdx.y ? cur2 : cur1;
    int i = blockIdx.x * blockDim.x + threadIdx.x;
    int stride = gridDim.x * blockDim.x;
    for (; i < N; i += stride) {
        int o = off[i] + pb[i >> 9];
        off[i] = o;
        cur[i] = o;
    }
}

__global__ void fill_dual(
    const int* __restrict__ s1, const int* __restrict__ d1, const float* __restrict__ w1,
    int E1, int* __restrict__ c1, int2* __restrict__ eo1,
    const int* __restrict__ s2, const int* __restrict__ d2, const float* __restrict__ w2,
    int E2, int* __restrict__ c2, int2* __restrict__ eo2)
{
    int i = blockIdx.x * blockDim.x + threadIdx.x;
    int stride = gridDim.x * blockDim.x;
    const int q1 = E1 >> 2, q2 = E2 >> 2;
    const int total = q1 + q2;
    for (int j = i; j < total; j += stride) {
        if (j < q1) {
            int4   dv = __ldg((const int4*)d1 + j);
            int4   sv = __ldg((const int4*)s1 + j);
            float4 wv = __ldg((const float4*)w1 + j);
            int p;
            p = atomicAdd(&c1[dv.x], 1); eo1[p] = make_int2(sv.x, __float_as_int(wv.x));
            p = atomicAdd(&c1[dv.y], 1); eo1[p] = make_int2(sv.y, __float_as_int(wv.y));
            p = atomicAdd(&c1[dv.z], 1); eo1[p] = make_int2(sv.z, __float_as_int(wv.z));
            p = atomicAdd(&c1[dv.w], 1); eo1[p] = make_int2(sv.w, __float_as_int(wv.w));
        } else {
            int k = j - q1;
            int4   dv = __ldg((const int4*)d2 + k);
            int4   sv = __ldg((const int4*)s2 + k);
            float4 wv = __ldg((const float4*)w2 + k);
            int p;
            p = atomicAdd(&c2[dv.x], 1); eo2[p] = make_int2(sv.x, __float_as_int(wv.x));
            p = atomicAdd(&c2[dv.y], 1); eo2[p] = make_int2(sv.y, __float_as_int(wv.y));
            p = atomicAdd(&c2[dv.z], 1); eo2[p] = make_int2(sv.z, __float_as_int(wv.z));
            p = atomicAdd(&c2[dv.w], 1); eo2[p] = make_int2(sv.w, __float_as_int(wv.w));
        }
    }
    if (i < (E1 & 3)) {
        int k = (q1 << 2) + i;
        int p = atomicAdd(&c1[d1[k]], 1);
        eo1[p] = make_int2(s1[k], __float_as_int(w1[k]));
    } else if (i >= 4 && i - 4 < (E2 & 3)) {
        int k = (q2 << 2) + (i - 4);
        int p = atomicAdd(&c2[d2[k]], 1);
        eo2[p] = make_int2(s2[k], __float_as_int(w2[k]));
    }
}

// -------------------------- fp32 -> fp16 mirror ------------------------------
__global__ void f32_to_f16(const float4* __restrict__ x, uint2* __restrict__ out, int n4)
{
    int i = blockIdx.x * blockDim.x + threadIdx.x;
    int stride = gridDim.x * blockDim.x;
    for (; i < n4; i += stride) {
        float4 v = __ldg(x + i);
        __half2 h0 = __floats2half2_rn(v.x, v.y);
        __half2 h1 = __floats2half2_rn(v.z, v.w);
        out[i] = make_uint2(*(uint32_t*)&h0, *(uint32_t*)&h1);
    }
}

// -------------------------- CSR gather SpMM (fp16, 2 rows/warp) --------------
// Each half-warp owns one row: 16 lanes x uint4 (8 fp16) = 256B row.
// fp32 accumulate, fp16 out. Uniform outer loop over max(deg) of the two rows.
__global__ void __launch_bounds__(512) spmm_gather(
    const uint4* __restrict__ xh,            // [N*16], each uint4 = 8 fp16
    const int* __restrict__ off, const int* __restrict__ end,
    const int2* __restrict__ edges,
    uint4* __restrict__ outh, int N)         // fp16 out, 8 halves per lane
{
    __shared__ int2 se[16][32];

    const int wid  = threadIdx.x >> 5;
    const int lane = threadIdx.x & 31;
    const int half = lane >> 4;              // 0 or 1
    const int hl   = lane & 15;              // lane within half-warp
    const int row  = blockIdx.x * 32 + wid * 2 + half;

    int beg = 0, deg = 0;
    if (row < N) {
        beg = __ldg(off + row);
        deg = __ldg(end + row) - beg;
    }
    const int dmax = max(deg, __shfl_xor_sync(0xffffffffu, deg, 16));
    if (dmax == 0) {
        if (row < N) {
            uint4 z = make_uint4(0u, 0u, 0u, 0u);
            outh[(size_t)row * 16 + hl] = z;
        }
        return;
    }

    float acc[8];
#pragma unroll
    for (int q = 0; q < 8; q++) acc[q] = 0.f;

    for (int j = 0; j < dmax; j += 16) {
        int cnt = deg - j;
        cnt = (cnt < 0) ? 0 : ((cnt > 16) ? 16 : cnt);
        int2 e = make_int2(0, 0);                 // w = 0 pad -> contributes 0
        if (hl < cnt) e = __ldg(edges + beg + j + hl);
        se[wid][lane] = e;
        __syncwarp();

        const int cnt8 = (cnt + 7) & ~7;
#pragma unroll 1
        for (int t = 0; t < cnt8; t += 8) {
            uint4 raw[8];
            float w[8];
#pragma unroll
            for (int u = 0; u < 8; u++) {
                int2 ee = se[wid][(half << 4) + t + u];
                w[u] = __int_as_float(ee.y);
                raw[u] = __ldg(xh + (size_t)ee.x * 16 + hl);
            }
#pragma unroll
            for (int u = 0; u < 8; u++) {
                float2 a = __half22float2(*reinterpret_cast<__half2*>(&raw[u].x));
                float2 b = __half22float2(*reinterpret_cast<__half2*>(&raw[u].y));
                float2 c = __half22float2(*reinterpret_cast<__half2*>(&raw[u].z));
                float2 d = __half22float2(*reinterpret_cast<__half2*>(&raw[u].w));
                acc[0] += w[u] * a.x;  acc[1] += w[u] * a.y;
                acc[2] += w[u] * b.x;  acc[3] += w[u] * b.y;
                acc[4] += w[u] * c.x;  acc[5] += w[u] * c.y;
                acc[6] += w[u] * d.x;  acc[7] += w[u] * d.y;
            }
        }
        __syncwarp();
    }

    if (row < N) {
        __half2 h0 = __floats2half2_rn(acc[0], acc[1]);
        __half2 h1 = __floats2half2_rn(acc[2], acc[3]);
        __half2 h2 = __floats2half2_rn(acc[4], acc[5]);
        __half2 h3 = __floats2half2_rn(acc[6], acc[7]);
        outh[(size_t)row * 16 + hl] =
            make_uint4(*(uint32_t*)&h0, *(uint32_t*)&h1,
                       *(uint32_t*)&h2, *(uint32_t*)&h3);
    }
}

// ---------------------- tensor-core fused 3-source GEMM ---------------------
// All A sources fp16 (xh, s1h, s2h). C fp32 out; optional fp16 mirror (written
// back into xh) for the next layer's gather.
__device__ __forceinline__ void ldsm_x4(uint32_t* r, uint32_t addr) {
    asm volatile("ldmatrix.sync.aligned.m8n8.x4.shared.b16 {%0,%1,%2,%3}, [%4];"
                 : "=r"(r[0]), "=r"(r[1]), "=r"(r[2]), "=r"(r[3]) : "r"(addr));
}
__device__ __forceinline__ void ldsm_x2t(uint32_t& r0, uint32_t& r1, uint32_t addr) {
    asm volatile("ldmatrix.sync.aligned.m8n8.x2.trans.shared.b16 {%0,%1}, [%2];"
                 : "=r"(r0), "=r"(r1) : "r"(addr));
}
__device__ __forceinline__ void mma_bf16(float* d, const uint32_t* a, uint32_t b0, uint32_t b1) {
    asm volatile("mma.sync.aligned.m16n8k16.row.col.f32.bf16.bf16.f32 "
                 "{%0,%1,%2,%3}, {%4,%5,%6,%7}, {%8,%9}, {%0,%1,%2,%3};"
                 : "+f"(d[0]), "+f"(d[1]), "+f"(d[2]), "+f"(d[3])
                 : "r"(a[0]), "r"(a[1]), "r"(a[2]), "r"(a[3]), "r"(b0), "r"(b1));
}

#define A_STRIDE 24

__global__ void __launch_bounds__(256, 2) gemm3_tc(
    const __half* __restrict__ A0,
    const __half* __restrict__ A1, const __half* __restrict__ A2,
    const float* __restrict__ B0, const float* __restrict__ B1, const float* __restrict__ B2,
    const float* __restrict__ b0, const float* __restrict__ b1, const float* __restrict__ b2,
    float* __restrict__ C, __half* __restrict__ Ch, int writeh, int M)
{
    __shared__ __nv_bfloat16 Ahi[128 * A_STRIDE];
    __shared__ __nv_bfloat16 Alo[128 * A_STRIDE];
    __shared__ __nv_bfloat16 Bhi[16 * 128];
    __shared__ __nv_bfloat16 Blo[16 * 128];
    __shared__ float bsum[128];

    const int tid  = threadIdx.x;
    const int lane = tid & 31;
    const int wid  = tid >> 5;
    const int row0 = blockIdx.x * 128;

    const int wm = (wid >> 1) * 32;
    const int wn = (wid & 1) * 64;

    if (tid < 128) bsum[tid] = __ldg(b0 + tid) + __ldg(b1 + tid) + __ldg(b2 + tid);

    float acc[2][8][4];
#pragma unroll
    for (int mt = 0; mt < 2; mt++)
#pragma unroll
        for (int nt = 0; nt < 8; nt++)
#pragma unroll
            for (int q = 0; q < 4; q++) acc[mt][nt][q] = 0.f;

    const int alr   = tid >> 1;
    const int akoff = (tid & 1) * 8;
    const bool arow_ok = (row0 + alr) < M;
    const int bk = tid >> 4;
    const int bj = tid & 15;

    const uint32_t sAhi = (uint32_t)__cvta_generic_to_shared(Ahi);
    const uint32_t sAlo = (uint32_t)__cvta_generic_to_shared(Alo);
    const uint32_t sBhi = (uint32_t)__cvta_generic_to_shared(Bhi);
    const uint32_t sBlo = (uint32_t)__cvta_generic_to_shared(Blo);

    const __half* Alist[3] = {A0, A1, A2};
    const float*  Blist[3] = {B0, B1, B2};

    for (int s = 0; s < 3; s++) {
        const __half* A = Alist[s];
        const float*  B = Blist[s];

#pragma unroll 1
        for (int kk = 0; kk < 8; kk++) {
            const int k0 = kk * 16;
            __syncthreads();

            {
                float f[8] = {0, 0, 0, 0, 0, 0, 0, 0};
                if (arow_ok) {
                    const __half* ap = A + (size_t)(row0 + alr) * F + k0 + akoff;
                    uint4 hv = *reinterpret_cast<const uint4*>(ap);
                    float2 p0 = __half22float2(*reinterpret_cast<__half2*>(&hv.x));
                    float2 p1 = __half22float2(*reinterpret_cast<__half2*>(&hv.y));
                    float2 p2 = __half22float2(*reinterpret_cast<__half2*>(&hv.z));
                    float2 p3 = __half22float2(*reinterpret_cast<__half2*>(&hv.w));
                    f[0] = p0.x; f[1] = p0.y; f[2] = p1.x; f[3] = p1.y;
                    f[4] = p2.x; f[5] = p2.y; f[6] = p3.x; f[7] = p3.y;
                }
                union { __nv_bfloat16 b[8]; uint4 u; } H, L;
#pragma unroll
                for (int q = 0; q < 8; q++) {
                    H.b[q] = __float2bfloat16(f[q]);
                    L.b[q] = __float2bfloat16(f[q] - __bfloat162float(H.b[q]));
                }
                *reinterpret_cast<uint4*>(&Ahi[alr * A_STRIDE + akoff]) = H.u;
                *reinterpret_cast<uint4*>(&Alo[alr * A_STRIDE + akoff]) = L.u;
            }
            {
                const float* bp = B + (size_t)(k0 + bk) * F + bj * 8;
                float4 fa = *reinterpret_cast<const float4*>(bp);
                float4 fb = *reinterpret_cast<const float4*>(bp + 4);
                float f[8] = {fa.x, fa.y, fa.z, fa.w, fb.x, fb.y, fb.z, fb.w};
                union { __nv_bfloat16 b[8]; uint4 u; } H, L;
#pragma unroll
                for (int q = 0; q < 8; q++) {
                    H.b[q] = __float2bfloat16(f[q]);
                    L.b[q] = __float2bfloat16(f[q] - __bfloat162float(H.b[q]));
                }
                const int cpos = bk * 128 + ((bj ^ (bk & 7)) * 8);
                *reinterpret_cast<uint4*>(&Bhi[cpos]) = H.u;
                *reinterpret_cast<uint4*>(&Blo[cpos]) = L.u;
            }
            __syncthreads();

            uint32_t ahi[2][4], alo[2][4];
#pragma unroll
            for (int mt = 0; mt < 2; mt++) {
                const int rl = wm + mt * 16 + (lane & 15);
                const uint32_t aoff = (uint32_t)(rl * (A_STRIDE * 2)) + ((lane >> 4) << 4);
                ldsm_x4(ahi[mt], sAhi + aoff);
                ldsm_x4(alo[mt], sAlo + aoff);
            }
#pragma unroll
            for (int nt = 0; nt < 8; nt++) {
                const int kl = lane & 15;
                const int chunk = ((wn >> 3) + nt) ^ (kl & 7);
                const uint32_t boff = (uint32_t)(kl * 256) + (uint32_t)(chunk << 4);
                uint32_t bh0, bh1, bl0, bl1;
                ldsm_x2t(bh0, bh1, sBhi + boff);
                ldsm_x2t(bl0, bl1, sBlo + boff);
#pragma unroll
                for (int mt = 0; mt < 2; mt++) {
                    mma_bf16(acc[mt][nt], ahi[mt], bh0, bh1);
                    mma_bf16(acc[mt][nt], ahi[mt], bl0, bl1);
                    mma_bf16(acc[mt][nt], alo[mt], bh0, bh1);
                }
            }
        }
    }
    __syncthreads();

    const int g = lane >> 2;
    const int t = lane & 3;
#pragma unroll
    for (int mt = 0; mt < 2; mt++) {
        const int r0 = row0 + wm + mt * 16 + g;
        const int r1 = r0 + 8;
#pragma unroll
        for (int nt = 0; nt < 8; nt++) {
            const int c0 = wn + nt * 8 + 2 * t;
            const float bs0 = bsum[c0], bs1 = bsum[c0 + 1];
            if (r0 < M) {
                float2 v = make_float2(acc[mt][nt][0] + bs0, acc[mt][nt][1] + bs1);
                *reinterpret_cast<float2*>(C + (size_t)r0 * F + c0) = v;
                if (writeh) {
                    __half2 hv = __floats2half2_rn(v.x, v.y);
                    *reinterpret_cast<__half2*>(Ch + (size_t)r0 * F + c0) = hv;
                }
            }
            if (r1 < M) {
                float2 v = make_float2(acc[mt][nt][2] + bs0, acc[mt][nt][3] + bs1);
                *reinterpret_cast<float2*>(C + (size_t)r1 * F + c0) = v;
                if (writeh) {
                    __half2 hv = __floats2half2_rn(v.x, v.y);
                    *reinterpret_cast<__half2*>(Ch + (size_t)r1 * F + c0) = hv;
                }
            }
        }
    }
}

// ------------------------------- launcher ----------------------------------
extern "C" void kernel_launch(void* const* d_in, const int* in_sizes, int n_in,
                              void* d_out, int out_size)
{
    const float* x   = (const float*)d_in[0];
    const int*   ei1 = (const int*)  d_in[1];
    const float* ea1 = (const float*)d_in[2];
    const int*   ei2 = (const int*)  d_in[3];
    const float* ea2 = (const float*)d_in[4];

    const float* W[3][3];
    const float* Bv[3][3];
    for (int blk = 0; blk < 3; blk++)
        for (int p = 0; p < 3; p++) {
            W[blk][p]  = (const float*)d_in[5 + blk * 6 + p * 2];
            Bv[blk][p] = (const float*)d_in[5 + blk * 6 + p * 2 + 1];
        }

    const int Nn = in_sizes[0] / F;
    const int E1 = in_sizes[1] / 2;
    const int E2 = in_sizes[3] / 2;

    float *x1, *x2;
    __half *xh, *s1h, *s2h;
    int *off1, *cur1, *off2, *cur2, *part1, *part2;
    int2 *e1, *e2;
    cudaGetSymbolAddress((void**)&s1h, g_s1h);
    cudaGetSymbolAddress((void**)&s2h, g_s2h);
    cudaGetSymbolAddress((void**)&x1, g_x1);
    cudaGetSymbolAddress((void**)&x2, g_x2);
    cudaGetSymbolAddress((void**)&xh, g_xh);
    cudaGetSymbolAddress((void**)&off1, g_off1);
    cudaGetSymbolAddress((void**)&cur1, g_cur1);
    cudaGetSymbolAddress((void**)&off2, g_off2);
    cudaGetSymbolAddress((void**)&cur2, g_cur2);
    cudaGetSymbolAddress((void**)&e1, g_e1);
    cudaGetSymbolAddress((void**)&e2, g_e2);
    cudaGetSymbolAddress((void**)&part1, g_part1);
    cudaGetSymbolAddress((void**)&part2, g_part2);

    const int NB = (Nn + 511) / 512;

    // ---- CSR build + fp16 mirror of x (edges constant across blocks) ----
    cudaMemsetAsync(cur1, 0, Nn * sizeof(int), 0);
    cudaMemsetAsync(cur2, 0, Nn * sizeof(int), 0);
    f32_to_f16<<<1024, 256>>>((const float4*)x, (uint2*)xh, Nn * 32);
    hist_dual<<<1024, 256>>>(ei1 + E1, E1, cur1, ei2 + E2, E2, cur2);
    {
        dim3 gA(NB, 2);
        scanA_kernel<<<gA, 512>>>(cur1, off1, part1, cur2, off2, part2, Nn);
        scanB_kernel<<<2, 512>>>(part1, part2, NB);
        dim3 gC(256, 2);
        scanC_kernel<<<gC, 256>>>(off1, part1, cur1, off2, part2, cur2, Nn);
    }
    fill_dual<<<1024, 256>>>(ei1, ei1 + E1, ea1, E1, cur1, e1,
                             ei2, ei2 + E2, ea2, E2, cur2, e2);
    // after fill: cur[i] == off[i] + degree(i) == row end

    float* outs[3] = {x1, x2, (float*)d_out};
    const int sgrid = (Nn + 31) / 32;        // 2 rows per warp, 16 warps/block
    const int ggrid = (Nn + 127) / 128;

    for (int blk = 0; blk < 3; blk++) {
        spmm_gather<<<sgrid, 512>>>((const uint4*)xh, off1, cur1, e1,
                                    (uint4*)s1h, Nn);
        spmm_gather<<<sgrid, 512>>>((const uint4*)xh, off2, cur2, e2,
                                    (uint4*)s2h, Nn);
        gemm3_tc<<<ggrid, 256>>>(
            xh, s1h, s2h,
            W[blk][0], W[blk][1], W[blk][2],
            Bv[blk][0], Bv[blk][1], Bv[blk][2],
            outs[blk], xh, (blk < 2) ? 1 : 0, Nn);
    }
}

// round 15
// speedup vs baseline: 1.0491x; 1.0491x over previous
#include <cuda_runtime.h>
#include <cuda_bf16.h>
#include <cuda_fp16.h>
#include <cstdint>

#define NMAX 100000
#define EMAX 1700000
#define F 128

// ------------------------- device-global scratch ---------------------------
__device__ __half g_s1h[(size_t)NMAX * F];   // fp16 gathered s1
__device__ __half g_s2h[(size_t)NMAX * F];   // fp16 gathered s2
__device__ float  g_x1[(size_t)NMAX * F];    // (unused C target for blk<2)
__device__ __half g_xh[(size_t)NMAX * F];    // fp16 mirror of current layer input
__device__ int    g_off1[NMAX], g_cur1[NMAX];
__device__ int    g_off2[NMAX], g_cur2[NMAX];
__device__ int2   g_e1[EMAX], g_e2[EMAX];    // interleaved {src, w-bits}
__device__ int    g_part1[512], g_part2[512];

// ------------------------------- CSR build ---------------------------------
__global__ void hist_dual(const int* __restrict__ d1, int E1, int* __restrict__ c1,
                          const int* __restrict__ d2, int E2, int* __restrict__ c2)
{
    int i = blockIdx.x * blockDim.x + threadIdx.x;
    int stride = gridDim.x * blockDim.x;
    const int q1 = E1 >> 2, q2 = E2 >> 2;
    const int total = q1 + q2;
    for (int j = i; j < total; j += stride) {
        if (j < q1) {
            int4 v = __ldg((const int4*)d1 + j);
            atomicAdd(&c1[v.x], 1); atomicAdd(&c1[v.y], 1);
            atomicAdd(&c1[v.z], 1); atomicAdd(&c1[v.w], 1);
        } else {
            int4 v = __ldg((const int4*)d2 + (j - q1));
            atomicAdd(&c2[v.x], 1); atomicAdd(&c2[v.y], 1);
            atomicAdd(&c2[v.z], 1); atomicAdd(&c2[v.w], 1);
        }
    }
    if (i < (E1 & 3)) atomicAdd(&c1[d1[(q1 << 2) + i]], 1);
    else if (i >= 4 && i - 4 < (E2 & 3)) atomicAdd(&c2[d2[(q2 << 2) + i - 4]], 1);
}

__global__ void __launch_bounds__(512) scanA_kernel(
    const int* __restrict__ cnt1, int* __restrict__ off1, int* __restrict__ p1,
    const int* __restrict__ cnt2, int* __restrict__ off2, int* __restrict__ p2,
    int N)
{
    const int* cnt = blockIdx.y ? cnt2 : cnt1;
    int* off       = blockIdx.y ? off2 : off1;
    int* partial   = blockIdx.y ? p2   : p1;
    __shared__ int sh[512];
    int t = threadIdx.x;
    int i = blockIdx.x * 512 + t;
    int v = (i < N) ? cnt[i] : 0;
    sh[t] = v;
    __syncthreads();
#pragma unroll
    for (int d = 1; d < 512; d <<= 1) {
        int u = (t >= d) ? sh[t - d] : 0;
        __syncthreads();
        sh[t] += u;
        __syncthreads();
    }
    if (i < N) off[i] = sh[t] - v;
    if (t == 511) partial[blockIdx.x] = sh[511];
}

__global__ void __launch_bounds__(512) scanB_kernel(
    int* __restrict__ p1, int* __restrict__ p2, int NB)
{
    int* partial = blockIdx.x ? p2 : p1;
    __shared__ int sh[512];
    int t = threadIdx.x;
    int v = (t < NB) ? partial[t] : 0;
    sh[t] = v;
    __syncthreads();
#pragma unroll
    for (int d = 1; d < 512; d <<= 1) {
        int u = (t >= d) ? sh[t - d] : 0;
        __syncthreads();
        sh[t] += u;
        __syncthreads();
    }
    if (t < NB) partial[t] = sh[t] - v;
}

__global__ void scanC_kernel(int* __restrict__ off1, const int* __restrict__ p1,
                             int* __restrict__ cur1,
                             int* __restrict__ off2, const int* __restrict__ p2,
                             int* __restrict__ cur2, int N)
{
    int* off        = blockIdx.y ? off2 : off1;
    const int* pb   = blockIdx.y ? p2   : p1;
    int* cur        = blockIdx.y ? cur2 : cur1;
    int i = blockIdx.x * blockDim.x + threadIdx.x;
    int stride = gridDim.x * blockDim.x;
    for (; i < N; i += stride) {
        int o = off[i] + pb[i >> 9];
        off[i] = o;
        cur[i] = o;
    }
}

__global__ void fill_dual(
    const int* __restrict__ s1, const int* __restrict__ d1, const float* __restrict__ w1,
    int E1, int* __restrict__ c1, int2* __restrict__ eo1,
    const int* __restrict__ s2, const int* __restrict__ d2, const float* __restrict__ w2,
    int E2, int* __restrict__ c2, int2* __restrict__ eo2)
{
    int i = blockIdx.x * blockDim.x + threadIdx.x;
    int stride = gridDim.x * blockDim.x;
    const int q1 = E1 >> 2, q2 = E2 >> 2;
    const int total = q1 + q2;
    for (int j = i; j < total; j += stride) {
        if (j < q1) {
            int4   dv = __ldg((const int4*)d1 + j);
            int4   sv = __ldg((const int4*)s1 + j);
            float4 wv = __ldg((const float4*)w1 + j);
            int p;
            p = atomicAdd(&c1[dv.x], 1); eo1[p] = make_int2(sv.x, __float_as_int(wv.x));
            p = atomicAdd(&c1[dv.y], 1); eo1[p] = make_int2(sv.y, __float_as_int(wv.y));
            p = atomicAdd(&c1[dv.z], 1); eo1[p] = make_int2(sv.z, __float_as_int(wv.z));
            p = atomicAdd(&c1[dv.w], 1); eo1[p] = make_int2(sv.w, __float_as_int(wv.w));
        } else {
            int k = j - q1;
            int4   dv = __ldg((const int4*)d2 + k);
            int4   sv = __ldg((const int4*)s2 + k);
            float4 wv = __ldg((const float4*)w2 + k);
            int p;
            p = atomicAdd(&c2[dv.x], 1); eo2[p] = make_int2(sv.x, __float_as_int(wv.x));
            p = atomicAdd(&c2[dv.y], 1); eo2[p] = make_int2(sv.y, __float_as_int(wv.y));
            p = atomicAdd(&c2[dv.z], 1); eo2[p] = make_int2(sv.z, __float_as_int(wv.z));
            p = atomicAdd(&c2[dv.w], 1); eo2[p] = make_int2(sv.w, __float_as_int(wv.w));
        }
    }
    if (i < (E1 & 3)) {
        int k = (q1 << 2) + i;
        int p = atomicAdd(&c1[d1[k]], 1);
        eo1[p] = make_int2(s1[k], __float_as_int(w1[k]));
    } else if (i >= 4 && i - 4 < (E2 & 3)) {
        int k = (q2 << 2) + (i - 4);
        int p = atomicAdd(&c2[d2[k]], 1);
        eo2[p] = make_int2(s2[k], __float_as_int(w2[k]));
    }
}

// -------------------------- fp32 -> fp16 mirror ------------------------------
__global__ void f32_to_f16(const float4* __restrict__ x, uint2* __restrict__ out, int n4)
{
    int i = blockIdx.x * blockDim.x + threadIdx.x;
    int stride = gridDim.x * blockDim.x;
    for (; i < n4; i += stride) {
        float4 v = __ldg(x + i);
        __half2 h0 = __floats2half2_rn(v.x, v.y);
        __half2 h1 = __floats2half2_rn(v.z, v.w);
        out[i] = make_uint2(*(uint32_t*)&h0, *(uint32_t*)&h1);
    }
}

// -------------------------- CSR gather SpMM (fp16 in/out) --------------------
// out[row] = sum_{edges} w * xh[src]; warp per row, 4 halves per lane, MLP=8,
// smem-staged edge metadata with zero-weight padding. fp32 accumulate, fp16 out.
// (R13-exact: proven local optimum.)
__global__ void __launch_bounds__(512) spmm_gather(
    const uint2* __restrict__ xh,            // [N*32], each uint2 = 4 fp16
    const int* __restrict__ off, const int* __restrict__ end,
    const int2* __restrict__ edges,
    uint2* __restrict__ outh, int N)         // fp16 out, 4 halves per lane
{
    __shared__ int2 se[16][32];

    const int wid  = threadIdx.x >> 5;
    const int lane = threadIdx.x & 31;
    const int row  = blockIdx.x * 16 + wid;
    if (row >= N) return;

    const int beg = __ldg(off + row);
    const int en  = __ldg(end + row);

    float4 acc = make_float4(0.f, 0.f, 0.f, 0.f);

    for (int j = beg; j < en; j += 32) {
        const int cnt = min(32, en - j);
        int2 e = make_int2(0, 0);                 // w = 0.0f pad -> contributes 0
        if (lane < cnt) e = __ldg(edges + j + lane);
        se[wid][lane] = e;
        __syncwarp();

        const int cnt8 = (cnt + 7) & ~7;
#pragma unroll 1
        for (int t = 0; t < cnt8; t += 8) {
            uint2 raw[8];
            float w[8];
#pragma unroll
            for (int u = 0; u < 8; u++) {
                int2 ee = se[wid][t + u];
                w[u] = __int_as_float(ee.y);
                raw[u] = __ldg(xh + (size_t)ee.x * 32 + lane);
            }
#pragma unroll
            for (int u = 0; u < 8; u++) {
                float2 a = __half22float2(*reinterpret_cast<__half2*>(&raw[u].x));
                float2 b = __half22float2(*reinterpret_cast<__half2*>(&raw[u].y));
                acc.x += w[u] * a.x;
                acc.y += w[u] * a.y;
                acc.z += w[u] * b.x;
                acc.w += w[u] * b.y;
            }
        }
        __syncwarp();
    }
    __half2 h0 = __floats2half2_rn(acc.x, acc.y);
    __half2 h1 = __floats2half2_rn(acc.z, acc.w);
    outh[(size_t)row * 32 + lane] = make_uint2(*(uint32_t*)&h0, *(uint32_t*)&h1);
}

// ---------------------- tensor-core fused 3-source GEMM ---------------------
// All A sources fp16 (xh, s1h, s2h). Epilogue: fp32 store only when writef
// (final layer), fp16 mirror only when writeh (intermediate layers).
__device__ __forceinline__ void ldsm_x4(uint32_t* r, uint32_t addr) {
    asm volatile("ldmatrix.sync.aligned.m8n8.x4.shared.b16 {%0,%1,%2,%3}, [%4];"
                 : "=r"(r[0]), "=r"(r[1]), "=r"(r[2]), "=r"(r[3]) : "r"(addr));
}
__device__ __forceinline__ void ldsm_x2t(uint32_t& r0, uint32_t& r1, uint32_t addr) {
    asm volatile("ldmatrix.sync.aligned.m8n8.x2.trans.shared.b16 {%0,%1}, [%2];"
                 : "=r"(r0), "=r"(r1) : "r"(addr));
}
__device__ __forceinline__ void mma_bf16(float* d, const uint32_t* a, uint32_t b0, uint32_t b1) {
    asm volatile("mma.sync.aligned.m16n8k16.row.col.f32.bf16.bf16.f32 "
                 "{%0,%1,%2,%3}, {%4,%5,%6,%7}, {%8,%9}, {%0,%1,%2,%3};"
                 : "+f"(d[0]), "+f"(d[1]), "+f"(d[2]), "+f"(d[3])
                 : "r"(a[0]), "r"(a[1]), "r"(a[2]), "r"(a[3]), "r"(b0), "r"(b1));
}

#define A_STRIDE 24

__global__ void __launch_bounds__(256, 2) gemm3_tc(
    const __half* __restrict__ A0,
    const __half* __restrict__ A1, const __half* __restrict__ A2,
    const float* __restrict__ B0, const float* __restrict__ B1, const float* __restrict__ B2,
    const float* __restrict__ b0, const float* __restrict__ b1, const float* __restrict__ b2,
    float* __restrict__ C, __half* __restrict__ Ch, int writef, int writeh, int M)
{
    __shared__ __nv_bfloat16 Ahi[128 * A_STRIDE];
    __shared__ __nv_bfloat16 Alo[128 * A_STRIDE];
    __shared__ __nv_bfloat16 Bhi[16 * 128];
    __shared__ __nv_bfloat16 Blo[16 * 128];
    __shared__ float bsum[128];

    const int tid  = threadIdx.x;
    const int lane = tid & 31;
    const int wid  = tid >> 5;
    const int row0 = blockIdx.x * 128;

    const int wm = (wid >> 1) * 32;
    const int wn = (wid & 1) * 64;

    if (tid < 128) bsum[tid] = __ldg(b0 + tid) + __ldg(b1 + tid) + __ldg(b2 + tid);

    float acc[2][8][4];
#pragma unroll
    for (int mt = 0; mt < 2; mt++)
#pragma unroll
        for (int nt = 0; nt < 8; nt++)
#pragma unroll
            for (int q = 0; q < 4; q++) acc[mt][nt][q] = 0.f;

    const int alr   = tid >> 1;
    const int akoff = (tid & 1) * 8;
    const bool arow_ok = (row0 + alr) < M;
    const int bk = tid >> 4;
    const int bj = tid & 15;

    const uint32_t sAhi = (uint32_t)__cvta_generic_to_shared(Ahi);
    const uint32_t sAlo = (uint32_t)__cvta_generic_to_shared(Alo);
    const uint32_t sBhi = (uint32_t)__cvta_generic_to_shared(Bhi);
    const uint32_t sBlo = (uint32_t)__cvta_generic_to_shared(Blo);

    const __half* Alist[3] = {A0, A1, A2};
    const float*  Blist[3] = {B0, B1, B2};

    for (int s = 0; s < 3; s++) {
        const __half* A = Alist[s];
        const float*  B = Blist[s];

#pragma unroll 1
        for (int kk = 0; kk < 8; kk++) {
            const int k0 = kk * 16;
            __syncthreads();

            {
                float f[8] = {0, 0, 0, 0, 0, 0, 0, 0};
                if (arow_ok) {
                    const __half* ap = A + (size_t)(row0 + alr) * F + k0 + akoff;
                    uint4 hv = *reinterpret_cast<const uint4*>(ap);
                    float2 p0 = __half22float2(*reinterpret_cast<__half2*>(&hv.x));
                    float2 p1 = __half22float2(*reinterpret_cast<__half2*>(&hv.y));
                    float2 p2 = __half22float2(*reinterpret_cast<__half2*>(&hv.z));
                    float2 p3 = __half22float2(*reinterpret_cast<__half2*>(&hv.w));
                    f[0] = p0.x; f[1] = p0.y; f[2] = p1.x; f[3] = p1.y;
                    f[4] = p2.x; f[5] = p2.y; f[6] = p3.x; f[7] = p3.y;
                }
                union { __nv_bfloat16 b[8]; uint4 u; } H, L;
#pragma unroll
                for (int q = 0; q < 8; q++) {
                    H.b[q] = __float2bfloat16(f[q]);
                    L.b[q] = __float2bfloat16(f[q] - __bfloat162float(H.b[q]));
                }
                *reinterpret_cast<uint4*>(&Ahi[alr * A_STRIDE + akoff]) = H.u;
                *reinterpret_cast<uint4*>(&Alo[alr * A_STRIDE + akoff]) = L.u;
            }
            {
                const float* bp = B + (size_t)(k0 + bk) * F + bj * 8;
                float4 fa = *reinterpret_cast<const float4*>(bp);
                float4 fb = *reinterpret_cast<const float4*>(bp + 4);
                float f[8] = {fa.x, fa.y, fa.z, fa.w, fb.x, fb.y, fb.z, fb.w};
                union { __nv_bfloat16 b[8]; uint4 u; } H, L;
#pragma unroll
                for (int q = 0; q < 8; q++) {
                    H.b[q] = __float2bfloat16(f[q]);
                    L.b[q] = __float2bfloat16(f[q] - __bfloat162float(H.b[q]));
                }
                const int cpos = bk * 128 + ((bj ^ (bk & 7)) * 8);
                *reinterpret_cast<uint4*>(&Bhi[cpos]) = H.u;
                *reinterpret_cast<uint4*>(&Blo[cpos]) = L.u;
            }
            __syncthreads();

            uint32_t ahi[2][4], alo[2][4];
#pragma unroll
            for (int mt = 0; mt < 2; mt++) {
                const int rl = wm + mt * 16 + (lane & 15);
                const uint32_t aoff = (uint32_t)(rl * (A_STRIDE * 2)) + ((lane >> 4) << 4);
                ldsm_x4(ahi[mt], sAhi + aoff);
                ldsm_x4(alo[mt], sAlo + aoff);
            }
#pragma unroll
            for (int nt = 0; nt < 8; nt++) {
                const int kl = lane & 15;
                const int chunk = ((wn >> 3) + nt) ^ (kl & 7);
                const uint32_t boff = (uint32_t)(kl * 256) + (uint32_t)(chunk << 4);
                uint32_t bh0, bh1, bl0, bl1;
                ldsm_x2t(bh0, bh1, sBhi + boff);
                ldsm_x2t(bl0, bl1, sBlo + boff);
#pragma unroll
                for (int mt = 0; mt < 2; mt++) {
                    mma_bf16(acc[mt][nt], ahi[mt], bh0, bh1);
                    mma_bf16(acc[mt][nt], ahi[mt], bl0, bl1);
                    mma_bf16(acc[mt][nt], alo[mt], bh0, bh1);
                }
            }
        }
    }
    __syncthreads();

    const int g = lane >> 2;
    const int t = lane & 3;
#pragma unroll
    for (int mt = 0; mt < 2; mt++) {
        const int r0 = row0 + wm + mt * 16 + g;
        const int r1 = r0 + 8;
#pragma unroll
        for (int nt = 0; nt < 8; nt++) {
            const int c0 = wn + nt * 8 + 2 * t;
            const float bs0 = bsum[c0], bs1 = bsum[c0 + 1];
            if (r0 < M) {
                float2 v = make_float2(acc[mt][nt][0] + bs0, acc[mt][nt][1] + bs1);
                if (writef)
                    *reinterpret_cast<float2*>(C + (size_t)r0 * F + c0) = v;
                if (writeh) {
                    __half2 hv = __floats2half2_rn(v.x, v.y);
                    *reinterpret_cast<__half2*>(Ch + (size_t)r0 * F + c0) = hv;
                }
            }
            if (r1 < M) {
                float2 v = make_float2(acc[mt][nt][2] + bs0, acc[mt][nt][3] + bs1);
                if (writef)
                    *reinterpret_cast<float2*>(C + (size_t)r1 * F + c0) = v;
                if (writeh) {
                    __half2 hv = __floats2half2_rn(v.x, v.y);
                    *reinterpret_cast<__half2*>(Ch + (size_t)r1 * F + c0) = hv;
                }
            }
        }
    }
}

// ------------------------------- launcher ----------------------------------
extern "C" void kernel_launch(void* const* d_in, const int* in_sizes, int n_in,
                              void* d_out, int out_size)
{
    const float* x   = (const float*)d_in[0];
    const int*   ei1 = (const int*)  d_in[1];
    const float* ea1 = (const float*)d_in[2];
    const int*   ei2 = (const int*)  d_in[3];
    const float* ea2 = (const float*)d_in[4];

    const float* W[3][3];
    const float* Bv[3][3];
    for (int blk = 0; blk < 3; blk++)
        for (int p = 0; p < 3; p++) {
            W[blk][p]  = (const float*)d_in[5 + blk * 6 + p * 2];
            Bv[blk][p] = (const float*)d_in[5 + blk * 6 + p * 2 + 1];
        }

    const int Nn = in_sizes[0] / F;
    const int E1 = in_sizes[1] / 2;
    const int E2 = in_sizes[3] / 2;

    float* x1;
    __half *xh, *s1h, *s2h;
    int *off1, *cur1, *off2, *cur2, *part1, *part2;
    int2 *e1, *e2;
    cudaGetSymbolAddress((void**)&s1h, g_s1h);
    cudaGetSymbolAddress((void**)&s2h, g_s2h);
    cudaGetSymbolAddress((void**)&x1, g_x1);
    cudaGetSymbolAddress((void**)&xh, g_xh);
    cudaGetSymbolAddress((void**)&off1, g_off1);
    cudaGetSymbolAddress((void**)&cur1, g_cur1);
    cudaGetSymbolAddress((void**)&off2, g_off2);
    cudaGetSymbolAddress((void**)&cur2, g_cur2);
    cudaGetSymbolAddress((void**)&e1, g_e1);
    cudaGetSymbolAddress((void**)&e2, g_e2);
    cudaGetSymbolAddress((void**)&part1, g_part1);
    cudaGetSymbolAddress((void**)&part2, g_part2);

    const int NB = (Nn + 511) / 512;

    // ---- CSR build + fp16 mirror of x (edges constant across blocks) ----
    cudaMemsetAsync(cur1, 0, Nn * sizeof(int), 0);
    cudaMemsetAsync(cur2, 0, Nn * sizeof(int), 0);
    f32_to_f16<<<1024, 256>>>((const float4*)x, (uint2*)xh, Nn * 32);
    hist_dual<<<1024, 256>>>(ei1 + E1, E1, cur1, ei2 + E2, E2, cur2);
    {
        dim3 gA(NB, 2);
        scanA_kernel<<<gA, 512>>>(cur1, off1, part1, cur2, off2, part2, Nn);
        scanB_kernel<<<2, 512>>>(part1, part2, NB);
        dim3 gC(256, 2);
        scanC_kernel<<<gC, 256>>>(off1, part1, cur1, off2, part2, cur2, Nn);
    }
    fill_dual<<<1024, 256>>>(ei1, ei1 + E1, ea1, E1, cur1, e1,
                             ei2, ei2 + E2, ea2, E2, cur2, e2);
    // after fill: cur[i] == off[i] + degree(i) == row end

    const int sgrid = (Nn + 15) / 16;
    const int ggrid = (Nn + 127) / 128;

    for (int blk = 0; blk < 3; blk++) {
        spmm_gather<<<sgrid, 512>>>((const uint2*)xh, off1, cur1, e1,
                                    (uint2*)s1h, Nn);
        spmm_gather<<<sgrid, 512>>>((const uint2*)xh, off2, cur2, e2,
                                    (uint2*)s2h, Nn);
        const int last = (blk == 2);
        gemm3_tc<<<ggrid, 256>>>(
            xh, s1h, s2h,
            W[blk][0], W[blk][1], W[blk][2],
            Bv[blk][0], Bv[blk][1], Bv[blk][2],
            last ? (float*)d_out : x1, xh,
            /*writef=*/last, /*writeh=*/!last, Nn);
    }
}

// round 16
// speedup vs baseline: 1.0567x; 1.0072x over previous
#include <cuda_runtime.h>
#include <cuda_bf16.h>
#include <cuda_fp16.h>
#include <cstdint>

#define NMAX 100000
#define EMAX 1700000
#define F 128

// ------------------------- device-global scratch ---------------------------
__device__ __half g_s1h[(size_t)NMAX * F];   // fp16 gathered s1
__device__ __half g_s2h[(size_t)NMAX * F];   // fp16 gathered s2
__device__ float  g_x1[(size_t)NMAX * F];    // (unused C target for blk<2)
__device__ __half g_xh[(size_t)NMAX * F];    // fp16 mirror of current layer input
__device__ int    g_off1[NMAX], g_cur1[NMAX];
__device__ int    g_off2[NMAX], g_cur2[NMAX];
__device__ int2   g_e1[EMAX], g_e2[EMAX];    // interleaved {src, w-bits}
__device__ int    g_part1[512], g_part2[512];

// ---------------- prep: fp32 -> fp16 mirror + zero cur1/cur2 -----------------
__global__ void prep_kernel(const float4* __restrict__ x, uint2* __restrict__ out,
                            int n4, int* __restrict__ c1, int* __restrict__ c2, int N)
{
    int i = blockIdx.x * blockDim.x + threadIdx.x;
    int stride = gridDim.x * blockDim.x;
    for (int j = i; j < n4; j += stride) {
        float4 v = __ldg(x + j);
        __half2 h0 = __floats2half2_rn(v.x, v.y);
        __half2 h1 = __floats2half2_rn(v.z, v.w);
        out[j] = make_uint2(*(uint32_t*)&h0, *(uint32_t*)&h1);
    }
    for (int j = i; j < N; j += stride) {
        c1[j] = 0;
        c2[j] = 0;
    }
}

// ------------------------------- CSR build ---------------------------------
__global__ void hist_dual(const int* __restrict__ d1, int E1, int* __restrict__ c1,
                          const int* __restrict__ d2, int E2, int* __restrict__ c2)
{
    int i = blockIdx.x * blockDim.x + threadIdx.x;
    int stride = gridDim.x * blockDim.x;
    const int q1 = E1 >> 2, q2 = E2 >> 2;
    const int total = q1 + q2;
    for (int j = i; j < total; j += stride) {
        if (j < q1) {
            int4 v = __ldg((const int4*)d1 + j);
            atomicAdd(&c1[v.x], 1); atomicAdd(&c1[v.y], 1);
            atomicAdd(&c1[v.z], 1); atomicAdd(&c1[v.w], 1);
        } else {
            int4 v = __ldg((const int4*)d2 + (j - q1));
            atomicAdd(&c2[v.x], 1); atomicAdd(&c2[v.y], 1);
            atomicAdd(&c2[v.z], 1); atomicAdd(&c2[v.w], 1);
        }
    }
    if (i < (E1 & 3)) atomicAdd(&c1[d1[(q1 << 2) + i]], 1);
    else if (i >= 4 && i - 4 < (E2 & 3)) atomicAdd(&c2[d2[(q2 << 2) + i - 4]], 1);
}

__global__ void __launch_bounds__(512) scanA_kernel(
    const int* __restrict__ cnt1, int* __restrict__ off1, int* __restrict__ p1,
    const int* __restrict__ cnt2, int* __restrict__ off2, int* __restrict__ p2,
    int N)
{
    const int* cnt = blockIdx.y ? cnt2 : cnt1;
    int* off       = blockIdx.y ? off2 : off1;
    int* partial   = blockIdx.y ? p2   : p1;
    __shared__ int sh[512];
    int t = threadIdx.x;
    int i = blockIdx.x * 512 + t;
    int v = (i < N) ? cnt[i] : 0;
    sh[t] = v;
    __syncthreads();
#pragma unroll
    for (int d = 1; d < 512; d <<= 1) {
        int u = (t >= d) ? sh[t - d] : 0;
        __syncthreads();
        sh[t] += u;
        __syncthreads();
    }
    if (i < N) off[i] = sh[t] - v;
    if (t == 511) partial[blockIdx.x] = sh[511];
}

// scanC with folded partial-scan: each block replicates the tiny exclusive
// scan of the chunk totals in smem, then does its grid-stride fixup.
__global__ void __launch_bounds__(512) scanC_kernel(
    int* __restrict__ off1, const int* __restrict__ p1, int* __restrict__ cur1,
    int* __restrict__ off2, const int* __restrict__ p2, int* __restrict__ cur2,
    int N, int NB)
{
    int* off        = blockIdx.y ? off2 : off1;
    const int* pb   = blockIdx.y ? p2   : p1;
    int* cur        = blockIdx.y ? cur2 : cur1;

    __shared__ int sh[512];
    int t = threadIdx.x;
    int v = (t < NB) ? pb[t] : 0;
    sh[t] = v;
    __syncthreads();
#pragma unroll
    for (int d = 1; d < 512; d <<= 1) {
        int u = (t >= d) ? sh[t - d] : 0;
        __syncthreads();
        sh[t] += u;
        __syncthreads();
    }
    // sh[t] now inclusive; exclusive prefix of chunk c = sh[c] - pb[c]
    __shared__ int ex[512];
    ex[t] = sh[t] - v;
    __syncthreads();

    int i = blockIdx.x * blockDim.x + threadIdx.x;
    int stride = gridDim.x * blockDim.x;
    for (; i < N; i += stride) {
        int o = off[i] + ex[i >> 9];
        off[i] = o;
        cur[i] = o;
    }
}

__global__ void fill_dual(
    const int* __restrict__ s1, const int* __restrict__ d1, const float* __restrict__ w1,
    int E1, int* __restrict__ c1, int2* __restrict__ eo1,
    const int* __restrict__ s2, const int* __restrict__ d2, const float* __restrict__ w2,
    int E2, int* __restrict__ c2, int2* __restrict__ eo2)
{
    int i = blockIdx.x * blockDim.x + threadIdx.x;
    int stride = gridDim.x * blockDim.x;
    const int q1 = E1 >> 2, q2 = E2 >> 2;
    const int total = q1 + q2;
    for (int j = i; j < total; j += stride) {
        if (j < q1) {
            int4   dv = __ldg((const int4*)d1 + j);
            int4   sv = __ldg((const int4*)s1 + j);
            float4 wv = __ldg((const float4*)w1 + j);
            int p;
            p = atomicAdd(&c1[dv.x], 1); eo1[p] = make_int2(sv.x, __float_as_int(wv.x));
            p = atomicAdd(&c1[dv.y], 1); eo1[p] = make_int2(sv.y, __float_as_int(wv.y));
            p = atomicAdd(&c1[dv.z], 1); eo1[p] = make_int2(sv.z, __float_as_int(wv.z));
            p = atomicAdd(&c1[dv.w], 1); eo1[p] = make_int2(sv.w, __float_as_int(wv.w));
        } else {
            int k = j - q1;
            int4   dv = __ldg((const int4*)d2 + k);
            int4   sv = __ldg((const int4*)s2 + k);
            float4 wv = __ldg((const float4*)w2 + k);
            int p;
            p = atomicAdd(&c2[dv.x], 1); eo2[p] = make_int2(sv.x, __float_as_int(wv.x));
            p = atomicAdd(&c2[dv.y], 1); eo2[p] = make_int2(sv.y, __float_as_int(wv.y));
            p = atomicAdd(&c2[dv.z], 1); eo2[p] = make_int2(sv.z, __float_as_int(wv.z));
            p = atomicAdd(&c2[dv.w], 1); eo2[p] = make_int2(sv.w, __float_as_int(wv.w));
        }
    }
    if (i < (E1 & 3)) {
        int k = (q1 << 2) + i;
        int p = atomicAdd(&c1[d1[k]], 1);
        eo1[p] = make_int2(s1[k], __float_as_int(w1[k]));
    } else if (i >= 4 && i - 4 < (E2 & 3)) {
        int k = (q2 << 2) + (i - 4);
        int p = atomicAdd(&c2[d2[k]], 1);
        eo2[p] = make_int2(s2[k], __float_as_int(w2[k]));
    }
}

// -------------------------- CSR gather SpMM (fp16 in/out) --------------------
// (R13-exact: proven local optimum.)
__global__ void __launch_bounds__(512) spmm_gather(
    const uint2* __restrict__ xh,            // [N*32], each uint2 = 4 fp16
    const int* __restrict__ off, const int* __restrict__ end,
    const int2* __restrict__ edges,
    uint2* __restrict__ outh, int N)         // fp16 out, 4 halves per lane
{
    __shared__ int2 se[16][32];

    const int wid  = threadIdx.x >> 5;
    const int lane = threadIdx.x & 31;
    const int row  = blockIdx.x * 16 + wid;
    if (row >= N) return;

    const int beg = __ldg(off + row);
    const int en  = __ldg(end + row);

    float4 acc = make_float4(0.f, 0.f, 0.f, 0.f);

    for (int j = beg; j < en; j += 32) {
        const int cnt = min(32, en - j);
        int2 e = make_int2(0, 0);                 // w = 0.0f pad -> contributes 0
        if (lane < cnt) e = __ldg(edges + j + lane);
        se[wid][lane] = e;
        __syncwarp();

        const int cnt8 = (cnt + 7) & ~7;
#pragma unroll 1
        for (int t = 0; t < cnt8; t += 8) {
            uint2 raw[8];
            float w[8];
#pragma unroll
            for (int u = 0; u < 8; u++) {
                int2 ee = se[wid][t + u];
                w[u] = __int_as_float(ee.y);
                raw[u] = __ldg(xh + (size_t)ee.x * 32 + lane);
            }
#pragma unroll
            for (int u = 0; u < 8; u++) {
                float2 a = __half22float2(*reinterpret_cast<__half2*>(&raw[u].x));
                float2 b = __half22float2(*reinterpret_cast<__half2*>(&raw[u].y));
                acc.x += w[u] * a.x;
                acc.y += w[u] * a.y;
                acc.z += w[u] * b.x;
                acc.w += w[u] * b.y;
            }
        }
        __syncwarp();
    }
    __half2 h0 = __floats2half2_rn(acc.x, acc.y);
    __half2 h1 = __floats2half2_rn(acc.z, acc.w);
    outh[(size_t)row * 32 + lane] = make_uint2(*(uint32_t*)&h0, *(uint32_t*)&h1);
}

// ---------------------- tensor-core fused 3-source GEMM ---------------------
__device__ __forceinline__ void ldsm_x4(uint32_t* r, uint32_t addr) {
    asm volatile("ldmatrix.sync.aligned.m8n8.x4.shared.b16 {%0,%1,%2,%3}, [%4];"
                 : "=r"(r[0]), "=r"(r[1]), "=r"(r[2]), "=r"(r[3]) : "r"(addr));
}
__device__ __forceinline__ void ldsm_x2t(uint32_t& r0, uint32_t& r1, uint32_t addr) {
    asm volatile("ldmatrix.sync.aligned.m8n8.x2.trans.shared.b16 {%0,%1}, [%2];"
                 : "=r"(r0), "=r"(r1) : "r"(addr));
}
__device__ __forceinline__ void mma_bf16(float* d, const uint32_t* a, uint32_t b0, uint32_t b1) {
    asm volatile("mma.sync.aligned.m16n8k16.row.col.f32.bf16.bf16.f32 "
                 "{%0,%1,%2,%3}, {%4,%5,%6,%7}, {%8,%9}, {%0,%1,%2,%3};"
                 : "+f"(d[0]), "+f"(d[1]), "+f"(d[2]), "+f"(d[3])
                 : "r"(a[0]), "r"(a[1]), "r"(a[2]), "r"(a[3]), "r"(b0), "r"(b1));
}

#define A_STRIDE 24

__global__ void __launch_bounds__(256, 2) gemm3_tc(
    const __half* __restrict__ A0,
    const __half* __restrict__ A1, const __half* __restrict__ A2,
    const float* __restrict__ B0, const float* __restrict__ B1, const float* __restrict__ B2,
    const float* __restrict__ b0, const float* __restrict__ b1, const float* __restrict__ b2,
    float* __restrict__ C, __half* __restrict__ Ch, int writef, int writeh, int M)
{
    __shared__ __nv_bfloat16 Ahi[128 * A_STRIDE];
    __shared__ __nv_bfloat16 Alo[128 * A_STRIDE];
    __shared__ __nv_bfloat16 Bhi[16 * 128];
    __shared__ __nv_bfloat16 Blo[16 * 128];
    __shared__ float bsum[128];

    const int tid  = threadIdx.x;
    const int lane = tid & 31;
    const int wid  = tid >> 5;
    const int row0 = blockIdx.x * 128;

    const int wm = (wid >> 1) * 32;
    const int wn = (wid & 1) * 64;

    if (tid < 128) bsum[tid] = __ldg(b0 + tid) + __ldg(b1 + tid) + __ldg(b2 + tid);

    float acc[2][8][4];
#pragma unroll
    for (int mt = 0; mt < 2; mt++)
#pragma unroll
        for (int nt = 0; nt < 8; nt++)
#pragma unroll
            for (int q = 0; q < 4; q++) acc[mt][nt][q] = 0.f;

    const int alr   = tid >> 1;
    const int akoff = (tid & 1) * 8;
    const bool arow_ok = (row0 + alr) < M;
    const int bk = tid >> 4;
    const int bj = tid & 15;

    const uint32_t sAhi = (uint32_t)__cvta_generic_to_shared(Ahi);
    const uint32_t sAlo = (uint32_t)__cvta_generic_to_shared(Alo);
    const uint32_t sBhi = (uint32_t)__cvta_generic_to_shared(Bhi);
    const uint32_t sBlo = (uint32_t)__cvta_generic_to_shared(Blo);

    const __half* Alist[3] = {A0, A1, A2};
    const float*  Blist[3] = {B0, B1, B2};

    for (int s = 0; s < 3; s++) {
        const __half* A = Alist[s];
        const float*  B = Blist[s];

#pragma unroll 1
        for (int kk = 0; kk < 8; kk++) {
            const int k0 = kk * 16;
            __syncthreads();

            {
                float f[8] = {0, 0, 0, 0, 0, 0, 0, 0};
                if (arow_ok) {
                    const __half* ap = A + (size_t)(row0 + alr) * F + k0 + akoff;
                    uint4 hv = *reinterpret_cast<const uint4*>(ap);
                    float2 p0 = __half22float2(*reinterpret_cast<__half2*>(&hv.x));
                    float2 p1 = __half22float2(*reinterpret_cast<__half2*>(&hv.y));
                    float2 p2 = __half22float2(*reinterpret_cast<__half2*>(&hv.z));
                    float2 p3 = __half22float2(*reinterpret_cast<__half2*>(&hv.w));
                    f[0] = p0.x; f[1] = p0.y; f[2] = p1.x; f[3] = p1.y;
                    f[4] = p2.x; f[5] = p2.y; f[6] = p3.x; f[7] = p3.y;
                }
                union { __nv_bfloat16 b[8]; uint4 u; } H, L;
#pragma unroll
                for (int q = 0; q < 8; q++) {
                    H.b[q] = __float2bfloat16(f[q]);
                    L.b[q] = __float2bfloat16(f[q] - __bfloat162float(H.b[q]));
                }
                *reinterpret_cast<uint4*>(&Ahi[alr * A_STRIDE + akoff]) = H.u;
                *reinterpret_cast<uint4*>(&Alo[alr * A_STRIDE + akoff]) = L.u;
            }
            {
                const float* bp = B + (size_t)(k0 + bk) * F + bj * 8;
                float4 fa = *reinterpret_cast<const float4*>(bp);
                float4 fb = *reinterpret_cast<const float4*>(bp + 4);
                float f[8] = {fa.x, fa.y, fa.z, fa.w, fb.x, fb.y, fb.z, fb.w};
                union { __nv_bfloat16 b[8]; uint4 u; } H, L;
#pragma unroll
                for (int q = 0; q < 8; q++) {
                    H.b[q] = __float2bfloat16(f[q]);
                    L.b[q] = __float2bfloat16(f[q] - __bfloat162float(H.b[q]));
                }
                const int cpos = bk * 128 + ((bj ^ (bk & 7)) * 8);
                *reinterpret_cast<uint4*>(&Bhi[cpos]) = H.u;
                *reinterpret_cast<uint4*>(&Blo[cpos]) = L.u;
            }
            __syncthreads();

            uint32_t ahi[2][4], alo[2][4];
#pragma unroll
            for (int mt = 0; mt < 2; mt++) {
                const int rl = wm + mt * 16 + (lane & 15);
                const uint32_t aoff = (uint32_t)(rl * (A_STRIDE * 2)) + ((lane >> 4) << 4);
                ldsm_x4(ahi[mt], sAhi + aoff);
                ldsm_x4(alo[mt], sAlo + aoff);
            }
#pragma unroll
            for (int nt = 0; nt < 8; nt++) {
                const int kl = lane & 15;
                const int chunk = ((wn >> 3) + nt) ^ (kl & 7);
                const uint32_t boff = (uint32_t)(kl * 256) + (uint32_t)(chunk << 4);
                uint32_t bh0, bh1, bl0, bl1;
                ldsm_x2t(bh0, bh1, sBhi + boff);
                ldsm_x2t(bl0, bl1, sBlo + boff);
#pragma unroll
                for (int mt = 0; mt < 2; mt++) {
                    mma_bf16(acc[mt][nt], ahi[mt], bh0, bh1);
                    mma_bf16(acc[mt][nt], ahi[mt], bl0, bl1);
                    mma_bf16(acc[mt][nt], alo[mt], bh0, bh1);
                }
            }
        }
    }
    __syncthreads();

    const int g = lane >> 2;
    const int t = lane & 3;
#pragma unroll
    for (int mt = 0; mt < 2; mt++) {
        const int r0 = row0 + wm + mt * 16 + g;
        const int r1 = r0 + 8;
#pragma unroll
        for (int nt = 0; nt < 8; nt++) {
            const int c0 = wn + nt * 8 + 2 * t;
            const float bs0 = bsum[c0], bs1 = bsum[c0 + 1];
            if (r0 < M) {
                float2 v = make_float2(acc[mt][nt][0] + bs0, acc[mt][nt][1] + bs1);
                if (writef)
                    *reinterpret_cast<float2*>(C + (size_t)r0 * F + c0) = v;
                if (writeh) {
                    __half2 hv = __floats2half2_rn(v.x, v.y);
                    *reinterpret_cast<__half2*>(Ch + (size_t)r0 * F + c0) = hv;
                }
            }
            if (r1 < M) {
                float2 v = make_float2(acc[mt][nt][2] + bs0, acc[mt][nt][3] + bs1);
                if (writef)
                    *reinterpret_cast<float2*>(C + (size_t)r1 * F + c0) = v;
                if (writeh) {
                    __half2 hv = __floats2half2_rn(v.x, v.y);
                    *reinterpret_cast<__half2*>(Ch + (size_t)r1 * F + c0) = hv;
                }
            }
        }
    }
}

// ------------------------------- launcher ----------------------------------
extern "C" void kernel_launch(void* const* d_in, const int* in_sizes, int n_in,
                              void* d_out, int out_size)
{
    const float* x   = (const float*)d_in[0];
    const int*   ei1 = (const int*)  d_in[1];
    const float* ea1 = (const float*)d_in[2];
    const int*   ei2 = (const int*)  d_in[3];
    const float* ea2 = (const float*)d_in[4];

    const float* W[3][3];
    const float* Bv[3][3];
    for (int blk = 0; blk < 3; blk++)
        for (int p = 0; p < 3; p++) {
            W[blk][p]  = (const float*)d_in[5 + blk * 6 + p * 2];
            Bv[blk][p] = (const float*)d_in[5 + blk * 6 + p * 2 + 1];
        }

    const int Nn = in_sizes[0] / F;
    const int E1 = in_sizes[1] / 2;
    const int E2 = in_sizes[3] / 2;

    float* x1;
    __half *xh, *s1h, *s2h;
    int *off1, *cur1, *off2, *cur2, *part1, *part2;
    int2 *e1, *e2;
    cudaGetSymbolAddress((void**)&s1h, g_s1h);
    cudaGetSymbolAddress((void**)&s2h, g_s2h);
    cudaGetSymbolAddress((void**)&x1, g_x1);
    cudaGetSymbolAddress((void**)&xh, g_xh);
    cudaGetSymbolAddress((void**)&off1, g_off1);
    cudaGetSymbolAddress((void**)&cur1, g_cur1);
    cudaGetSymbolAddress((void**)&off2, g_off2);
    cudaGetSymbolAddress((void**)&cur2, g_cur2);
    cudaGetSymbolAddress((void**)&e1, g_e1);
    cudaGetSymbolAddress((void**)&e2, g_e2);
    cudaGetSymbolAddress((void**)&part1, g_part1);
    cudaGetSymbolAddress((void**)&part2, g_part2);

    const int NB = (Nn + 511) / 512;

    // ---- prep (f16 mirror + zero counters) + CSR build ----
    prep_kernel<<<1024, 256>>>((const float4*)x, (uint2*)xh, Nn * 32,
                               cur1, cur2, Nn);
    hist_dual<<<1024, 256>>>(ei1 + E1, E1, cur1, ei2 + E2, E2, cur2);
    {
        dim3 gA(NB, 2);
        scanA_kernel<<<gA, 512>>>(cur1, off1, part1, cur2, off2, part2, Nn);
        dim3 gC(128, 2);
        scanC_kernel<<<gC, 512>>>(off1, part1, cur1, off2, part2, cur2, Nn, NB);
    }
    fill_dual<<<1024, 256>>>(ei1, ei1 + E1, ea1, E1, cur1, e1,
                             ei2, ei2 + E2, ea2, E2, cur2, e2);
    // after fill: cur[i] == off[i] + degree(i) == row end

    const int sgrid = (Nn + 15) / 16;
    const int ggrid = (Nn + 127) / 128;

    for (int blk = 0; blk < 3; blk++) {
        spmm_gather<<<sgrid, 512>>>((const uint2*)xh, off1, cur1, e1,
                                    (uint2*)s1h, Nn);
        spmm_gather<<<sgrid, 512>>>((const uint2*)xh, off2, cur2, e2,
                                    (uint2*)s2h, Nn);
        const int last = (blk == 2);
        gemm3_tc<<<ggrid, 256>>>(
            xh, s1h, s2h,
            W[blk][0], W[blk][1], W[blk][2],
            Bv[blk][0], Bv[blk][1], Bv[blk][2],
            last ? (float*)d_out : x1, xh,
            /*writef=*/last, /*writeh=*/!last, Nn);
    }
}

// round 17
// speedup vs baseline: 1.1542x; 1.0923x over previous
#include <cuda_runtime.h>
#include <cuda_bf16.h>
#include <cuda_fp16.h>
#include <cstdint>

#define NMAX 100000
#define EMAX 1700000
#define F 128

// ------------------------- device-global scratch ---------------------------
__device__ __half g_s1h[(size_t)NMAX * F];   // fp16 gathered s1
__device__ __half g_s2h[(size_t)NMAX * F];   // fp16 gathered s2
__device__ float  g_x1[(size_t)NMAX * F];    // (unused C target for blk<2)
__device__ __half g_xh[(size_t)NMAX * F];    // fp16 mirror of current layer input
__device__ int    g_off1[NMAX], g_cur1[NMAX];
__device__ int    g_off2[NMAX], g_cur2[NMAX];
__device__ int2   g_e1[EMAX], g_e2[EMAX];    // interleaved {src, w-bits}
__device__ int    g_part1[512], g_part2[512];

// ---------------- prep: fp32 -> fp16 mirror + zero cur1/cur2 -----------------
__global__ void prep_kernel(const float4* __restrict__ x, uint2* __restrict__ out,
                            int n4, int* __restrict__ c1, int* __restrict__ c2, int N)
{
    int i = blockIdx.x * blockDim.x + threadIdx.x;
    int stride = gridDim.x * blockDim.x;
    for (int j = i; j < n4; j += stride) {
        float4 v = __ldg(x + j);
        __half2 h0 = __floats2half2_rn(v.x, v.y);
        __half2 h1 = __floats2half2_rn(v.z, v.w);
        out[j] = make_uint2(*(uint32_t*)&h0, *(uint32_t*)&h1);
    }
    for (int j = i; j < N; j += stride) {
        c1[j] = 0;
        c2[j] = 0;
    }
}

// ------------------------------- CSR build ---------------------------------
__global__ void hist_dual(const int* __restrict__ d1, int E1, int* __restrict__ c1,
                          const int* __restrict__ d2, int E2, int* __restrict__ c2)
{
    int i = blockIdx.x * blockDim.x + threadIdx.x;
    int stride = gridDim.x * blockDim.x;
    const int q1 = E1 >> 2, q2 = E2 >> 2;
    const int total = q1 + q2;
    for (int j = i; j < total; j += stride) {
        if (j < q1) {
            int4 v = __ldg((const int4*)d1 + j);
            atomicAdd(&c1[v.x], 1); atomicAdd(&c1[v.y], 1);
            atomicAdd(&c1[v.z], 1); atomicAdd(&c1[v.w], 1);
        } else {
            int4 v = __ldg((const int4*)d2 + (j - q1));
            atomicAdd(&c2[v.x], 1); atomicAdd(&c2[v.y], 1);
            atomicAdd(&c2[v.z], 1); atomicAdd(&c2[v.w], 1);
        }
    }
    if (i < (E1 & 3)) atomicAdd(&c1[d1[(q1 << 2) + i]], 1);
    else if (i >= 4 && i - 4 < (E2 & 3)) atomicAdd(&c2[d2[(q2 << 2) + i - 4]], 1);
}

__global__ void __launch_bounds__(512) scanA_kernel(
    const int* __restrict__ cnt1, int* __restrict__ off1, int* __restrict__ p1,
    const int* __restrict__ cnt2, int* __restrict__ off2, int* __restrict__ p2,
    int N)
{
    const int* cnt = blockIdx.y ? cnt2 : cnt1;
    int* off       = blockIdx.y ? off2 : off1;
    int* partial   = blockIdx.y ? p2   : p1;
    __shared__ int sh[512];
    int t = threadIdx.x;
    int i = blockIdx.x * 512 + t;
    int v = (i < N) ? cnt[i] : 0;
    sh[t] = v;
    __syncthreads();
#pragma unroll
    for (int d = 1; d < 512; d <<= 1) {
        int u = (t >= d) ? sh[t - d] : 0;
        __syncthreads();
        sh[t] += u;
        __syncthreads();
    }
    if (i < N) off[i] = sh[t] - v;
    if (t == 511) partial[blockIdx.x] = sh[511];
}

// scanC with folded partial-scan
__global__ void __launch_bounds__(512) scanC_kernel(
    int* __restrict__ off1, const int* __restrict__ p1, int* __restrict__ cur1,
    int* __restrict__ off2, const int* __restrict__ p2, int* __restrict__ cur2,
    int N, int NB)
{
    int* off        = blockIdx.y ? off2 : off1;
    const int* pb   = blockIdx.y ? p2   : p1;
    int* cur        = blockIdx.y ? cur2 : cur1;

    __shared__ int sh[512];
    int t = threadIdx.x;
    int v = (t < NB) ? pb[t] : 0;
    sh[t] = v;
    __syncthreads();
#pragma unroll
    for (int d = 1; d < 512; d <<= 1) {
        int u = (t >= d) ? sh[t - d] : 0;
        __syncthreads();
        sh[t] += u;
        __syncthreads();
    }
    __shared__ int ex[512];
    ex[t] = sh[t] - v;
    __syncthreads();

    int i = blockIdx.x * blockDim.x + threadIdx.x;
    int stride = gridDim.x * blockDim.x;
    for (; i < N; i += stride) {
        int o = off[i] + ex[i >> 9];
        off[i] = o;
        cur[i] = o;
    }
}

__global__ void fill_dual(
    const int* __restrict__ s1, const int* __restrict__ d1, const float* __restrict__ w1,
    int E1, int* __restrict__ c1, int2* __restrict__ eo1,
    const int* __restrict__ s2, const int* __restrict__ d2, const float* __restrict__ w2,
    int E2, int* __restrict__ c2, int2* __restrict__ eo2)
{
    int i = blockIdx.x * blockDim.x + threadIdx.x;
    int stride = gridDim.x * blockDim.x;
    const int q1 = E1 >> 2, q2 = E2 >> 2;
    const int total = q1 + q2;
    for (int j = i; j < total; j += stride) {
        if (j < q1) {
            int4   dv = __ldg((const int4*)d1 + j);
            int4   sv = __ldg((const int4*)s1 + j);
            float4 wv = __ldg((const float4*)w1 + j);
            int p;
            p = atomicAdd(&c1[dv.x], 1); eo1[p] = make_int2(sv.x, __float_as_int(wv.x));
            p = atomicAdd(&c1[dv.y], 1); eo1[p] = make_int2(sv.y, __float_as_int(wv.y));
            p = atomicAdd(&c1[dv.z], 1); eo1[p] = make_int2(sv.z, __float_as_int(wv.z));
            p = atomicAdd(&c1[dv.w], 1); eo1[p] = make_int2(sv.w, __float_as_int(wv.w));
        } else {
            int k = j - q1;
            int4   dv = __ldg((const int4*)d2 + k);
            int4   sv = __ldg((const int4*)s2 + k);
            float4 wv = __ldg((const float4*)w2 + k);
            int p;
            p = atomicAdd(&c2[dv.x], 1); eo2[p] = make_int2(sv.x, __float_as_int(wv.x));
            p = atomicAdd(&c2[dv.y], 1); eo2[p] = make_int2(sv.y, __float_as_int(wv.y));
            p = atomicAdd(&c2[dv.z], 1); eo2[p] = make_int2(sv.z, __float_as_int(wv.z));
            p = atomicAdd(&c2[dv.w], 1); eo2[p] = make_int2(sv.w, __float_as_int(wv.w));
        }
    }
    if (i < (E1 & 3)) {
        int k = (q1 << 2) + i;
        int p = atomicAdd(&c1[d1[k]], 1);
        eo1[p] = make_int2(s1[k], __float_as_int(w1[k]));
    } else if (i >= 4 && i - 4 < (E2 & 3)) {
        int k = (q2 << 2) + (i - 4);
        int p = atomicAdd(&c2[d2[k]], 1);
        eo2[p] = make_int2(s2[k], __float_as_int(w2[k]));
    }
}

// -------------------------- CSR gather SpMM (fp16 in/out) --------------------
// (R13-exact: proven local optimum.)
__global__ void __launch_bounds__(512) spmm_gather(
    const uint2* __restrict__ xh,            // [N*32], each uint2 = 4 fp16
    const int* __restrict__ off, const int* __restrict__ end,
    const int2* __restrict__ edges,
    uint2* __restrict__ outh, int N)         // fp16 out, 4 halves per lane
{
    __shared__ int2 se[16][32];

    const int wid  = threadIdx.x >> 5;
    const int lane = threadIdx.x & 31;
    const int row  = blockIdx.x * 16 + wid;
    if (row >= N) return;

    const int beg = __ldg(off + row);
    const int en  = __ldg(end + row);

    float4 acc = make_float4(0.f, 0.f, 0.f, 0.f);

    for (int j = beg; j < en; j += 32) {
        const int cnt = min(32, en - j);
        int2 e = make_int2(0, 0);                 // w = 0.0f pad -> contributes 0
        if (lane < cnt) e = __ldg(edges + j + lane);
        se[wid][lane] = e;
        __syncwarp();

        const int cnt8 = (cnt + 7) & ~7;
#pragma unroll 1
        for (int t = 0; t < cnt8; t += 8) {
            uint2 raw[8];
            float w[8];
#pragma unroll
            for (int u = 0; u < 8; u++) {
                int2 ee = se[wid][t + u];
                w[u] = __int_as_float(ee.y);
                raw[u] = __ldg(xh + (size_t)ee.x * 32 + lane);
            }
#pragma unroll
            for (int u = 0; u < 8; u++) {
                float2 a = __half22float2(*reinterpret_cast<__half2*>(&raw[u].x));
                float2 b = __half22float2(*reinterpret_cast<__half2*>(&raw[u].y));
                acc.x += w[u] * a.x;
                acc.y += w[u] * a.y;
                acc.z += w[u] * b.x;
                acc.w += w[u] * b.y;
            }
        }
        __syncwarp();
    }
    __half2 h0 = __floats2half2_rn(acc.x, acc.y);
    __half2 h1 = __floats2half2_rn(acc.z, acc.w);
    outh[(size_t)row * 32 + lane] = make_uint2(*(uint32_t*)&h0, *(uint32_t*)&h1);
}

// ---------------------- tensor-core fused 3-source GEMM ---------------------
// A sources fp16 (exact fragments, no split). W fp32 -> fp16 hi/lo (2-pass).
// fp32 accumulate throughout.
__device__ __forceinline__ void ldsm_x4(uint32_t* r, uint32_t addr) {
    asm volatile("ldmatrix.sync.aligned.m8n8.x4.shared.b16 {%0,%1,%2,%3}, [%4];"
                 : "=r"(r[0]), "=r"(r[1]), "=r"(r[2]), "=r"(r[3]) : "r"(addr));
}
__device__ __forceinline__ void ldsm_x2t(uint32_t& r0, uint32_t& r1, uint32_t addr) {
    asm volatile("ldmatrix.sync.aligned.m8n8.x2.trans.shared.b16 {%0,%1}, [%2];"
                 : "=r"(r0), "=r"(r1) : "r"(addr));
}
__device__ __forceinline__ void mma_f16(float* d, const uint32_t* a, uint32_t b0, uint32_t b1) {
    asm volatile("mma.sync.aligned.m16n8k16.row.col.f32.f16.f16.f32 "
                 "{%0,%1,%2,%3}, {%4,%5,%6,%7}, {%8,%9}, {%0,%1,%2,%3};"
                 : "+f"(d[0]), "+f"(d[1]), "+f"(d[2]), "+f"(d[3])
                 : "r"(a[0]), "r"(a[1]), "r"(a[2]), "r"(a[3]), "r"(b0), "r"(b1));
}

#define A_STRIDE 24

__global__ void __launch_bounds__(256, 2) gemm3_tc(
    const __half* __restrict__ A0,
    const __half* __restrict__ A1, const __half* __restrict__ A2,
    const float* __restrict__ B0, const float* __restrict__ B1, const float* __restrict__ B2,
    const float* __restrict__ b0, const float* __restrict__ b1, const float* __restrict__ b2,
    float* __restrict__ C, __half* __restrict__ Ch, int writef, int writeh, int M)
{
    __shared__ __half Ah[128 * A_STRIDE];
    __shared__ __half Bhi[16 * 128];
    __shared__ __half Blo[16 * 128];
    __shared__ float bsum[128];

    const int tid  = threadIdx.x;
    const int lane = tid & 31;
    const int wid  = tid >> 5;
    const int row0 = blockIdx.x * 128;

    const int wm = (wid >> 1) * 32;
    const int wn = (wid & 1) * 64;

    if (tid < 128) bsum[tid] = __ldg(b0 + tid) + __ldg(b1 + tid) + __ldg(b2 + tid);

    float acc[2][8][4];
#pragma unroll
    for (int mt = 0; mt < 2; mt++)
#pragma unroll
        for (int nt = 0; nt < 8; nt++)
#pragma unroll
            for (int q = 0; q < 4; q++) acc[mt][nt][q] = 0.f;

    const int alr   = tid >> 1;
    const int akoff = (tid & 1) * 8;
    const bool arow_ok = (row0 + alr) < M;
    const int bk = tid >> 4;
    const int bj = tid & 15;

    const uint32_t sAh  = (uint32_t)__cvta_generic_to_shared(Ah);
    const uint32_t sBhi = (uint32_t)__cvta_generic_to_shared(Bhi);
    const uint32_t sBlo = (uint32_t)__cvta_generic_to_shared(Blo);

    const __half* Alist[3] = {A0, A1, A2};
    const float*  Blist[3] = {B0, B1, B2};

    for (int s = 0; s < 3; s++) {
        const __half* A = Alist[s];
        const float*  B = Blist[s];

#pragma unroll 1
        for (int kk = 0; kk < 8; kk++) {
            const int k0 = kk * 16;
            __syncthreads();

            {
                uint4 hv = make_uint4(0u, 0u, 0u, 0u);
                if (arow_ok)
                    hv = *reinterpret_cast<const uint4*>(
                        A + (size_t)(row0 + alr) * F + k0 + akoff);
                *reinterpret_cast<uint4*>(&Ah[alr * A_STRIDE + akoff]) = hv;
            }
            {
                const float* bp = B + (size_t)(k0 + bk) * F + bj * 8;
                float4 fa = *reinterpret_cast<const float4*>(bp);
                float4 fb = *reinterpret_cast<const float4*>(bp + 4);
                float f[8] = {fa.x, fa.y, fa.z, fa.w, fb.x, fb.y, fb.z, fb.w};
                union { __half h[8]; uint4 u; } H, L;
#pragma unroll
                for (int q = 0; q < 8; q++) {
                    H.h[q] = __float2half_rn(f[q]);
                    L.h[q] = __float2half_rn(f[q] - __half2float(H.h[q]));
                }
                const int cpos = bk * 128 + ((bj ^ (bk & 7)) * 8);
                *reinterpret_cast<uint4*>(&Bhi[cpos]) = H.u;
                *reinterpret_cast<uint4*>(&Blo[cpos]) = L.u;
            }
            __syncthreads();

            uint32_t a[2][4];
#pragma unroll
            for (int mt = 0; mt < 2; mt++) {
                const int rl = wm + mt * 16 + (lane & 15);
                const uint32_t aoff = (uint32_t)(rl * (A_STRIDE * 2)) + ((lane >> 4) << 4);
                ldsm_x4(a[mt], sAh + aoff);
            }
#pragma unroll
            for (int nt = 0; nt < 8; nt++) {
                const int kl = lane & 15;
                const int chunk = ((wn >> 3) + nt) ^ (kl & 7);
                const uint32_t boff = (uint32_t)(kl * 256) + (uint32_t)(chunk << 4);
                uint32_t bh0, bh1, bl0, bl1;
                ldsm_x2t(bh0, bh1, sBhi + boff);
                ldsm_x2t(bl0, bl1, sBlo + boff);
#pragma unroll
                for (int mt = 0; mt < 2; mt++) {
                    mma_f16(acc[mt][nt], a[mt], bh0, bh1);
                    mma_f16(acc[mt][nt], a[mt], bl0, bl1);
                }
            }
        }
    }
    __syncthreads();

    const int g = lane >> 2;
    const int t = lane & 3;
#pragma unroll
    for (int mt = 0; mt < 2; mt++) {
        const int r0 = row0 + wm + mt * 16 + g;
        const int r1 = r0 + 8;
#pragma unroll
        for (int nt = 0; nt < 8; nt++) {
            const int c0 = wn + nt * 8 + 2 * t;
            const float bs0 = bsum[c0], bs1 = bsum[c0 + 1];
            if (r0 < M) {
                float2 v = make_float2(acc[mt][nt][0] + bs0, acc[mt][nt][1] + bs1);
                if (writef)
                    *reinterpret_cast<float2*>(C + (size_t)r0 * F + c0) = v;
                if (writeh) {
                    __half2 hv = __floats2half2_rn(v.x, v.y);
                    *reinterpret_cast<__half2*>(Ch + (size_t)r0 * F + c0) = hv;
                }
            }
            if (r1 < M) {
                float2 v = make_float2(acc[mt][nt][2] + bs0, acc[mt][nt][3] + bs1);
                if (writef)
                    *reinterpret_cast<float2*>(C + (size_t)r1 * F + c0) = v;
                if (writeh) {
                    __half2 hv = __floats2half2_rn(v.x, v.y);
                    *reinterpret_cast<__half2*>(Ch + (size_t)r1 * F + c0) = hv;
                }
            }
        }
    }
}

// ------------------------------- launcher ----------------------------------
extern "C" void kernel_launch(void* const* d_in, const int* in_sizes, int n_in,
                              void* d_out, int out_size)
{
    const float* x   = (const float*)d_in[0];
    const int*   ei1 = (const int*)  d_in[1];
    const float* ea1 = (const float*)d_in[2];
    const int*   ei2 = (const int*)  d_in[3];
    const float* ea2 = (const float*)d_in[4];

    const float* W[3][3];
    const float* Bv[3][3];
    for (int blk = 0; blk < 3; blk++)
        for (int p = 0; p < 3; p++) {
            W[blk][p]  = (const float*)d_in[5 + blk * 6 + p * 2];
            Bv[blk][p] = (const float*)d_in[5 + blk * 6 + p * 2 + 1];
        }

    const int Nn = in_sizes[0] / F;
    const int E1 = in_sizes[1] / 2;
    const int E2 = in_sizes[3] / 2;

    float* x1;
    __half *xh, *s1h, *s2h;
    int *off1, *cur1, *off2, *cur2, *part1, *part2;
    int2 *e1, *e2;
    cudaGetSymbolAddress((void**)&s1h, g_s1h);
    cudaGetSymbolAddress((void**)&s2h, g_s2h);
    cudaGetSymbolAddress((void**)&x1, g_x1);
    cudaGetSymbolAddress((void**)&xh, g_xh);
    cudaGetSymbolAddress((void**)&off1, g_off1);
    cudaGetSymbolAddress((void**)&cur1, g_cur1);
    cudaGetSymbolAddress((void**)&off2, g_off2);
    cudaGetSymbolAddress((void**)&cur2, g_cur2);
    cudaGetSymbolAddress((void**)&e1, g_e1);
    cudaGetSymbolAddress((void**)&e2, g_e2);
    cudaGetSymbolAddress((void**)&part1, g_part1);
    cudaGetSymbolAddress((void**)&part2, g_part2);

    const int NB = (Nn + 511) / 512;

    // ---- prep (f16 mirror + zero counters) + CSR build ----
    prep_kernel<<<1024, 256>>>((const float4*)x, (uint2*)xh, Nn * 32,
                               cur1, cur2, Nn);
    hist_dual<<<1024, 256>>>(ei1 + E1, E1, cur1, ei2 + E2, E2, cur2);
    {
        dim3 gA(NB, 2);
        scanA_kernel<<<gA, 512>>>(cur1, off1, part1, cur2, off2, part2, Nn);
        dim3 gC(128, 2);
        scanC_kernel<<<gC, 512>>>(off1, part1, cur1, off2, part2, cur2, Nn, NB);
    }
    fill_dual<<<1024, 256>>>(ei1, ei1 + E1, ea1, E1, cur1, e1,
                             ei2, ei2 + E2, ea2, E2, cur2, e2);
    // after fill: cur[i] == off[i] + degree(i) == row end

    const int sgrid = (Nn + 15) / 16;
    const int ggrid = (Nn + 127) / 128;

    for (int blk = 0; blk < 3; blk++) {
        spmm_gather<<<sgrid, 512>>>((const uint2*)xh, off1, cur1, e1,
                                    (uint2*)s1h, Nn);
        spmm_gather<<<sgrid, 512>>>((const uint2*)xh, off2, cur2, e2,
                                    (uint2*)s2h, Nn);
        const int last = (blk == 2);
        gemm3_tc<<<ggrid, 256>>>(
            xh, s1h, s2h,
            W[blk][0], W[blk][1], W[blk][2],
            Bv[blk][0], Bv[blk][1], Bv[blk][2],
            last ? (float*)d_out : x1, xh,
            /*writef=*/last, /*writeh=*/!last, Nn);
    }
}